// round 16
// baseline (speedup 1.0000x reference)
#include <cuda_runtime.h>
#include <cuda_bf16.h>

// Analytic reduction of the 4-op "nibble machine":
//   t      = x3*(1 - x10) + x[b, tok=3, col=1]
//   rawsum = x4 + x0 * t
//   result = x5 + (k>=3 ? rawsum[b, k-3] : 0)
// all other 61 columns: identity copy.
//
// Warp-owns-TWO-rows variant: lane l owns floats [16l,16l+16) of rows 2w and
// 2w+1 (4 front-batched LDG.256 -> 256B in flight per thread). All
// cross-token operands via __shfl_sync, zero gather loads. Patch lanes are
// l%4==0 (token t=l/4). If the DRAM plateau (~81%) is latency-limited this
// raises per-SM outstanding bytes ~1.6x; if turnaround-limited it's neutral
// and the single-row R15 kernel is final.

constexpr int THREADS = 256;                  // 8 warps -> 16 rows per block
constexpr int ROWS_PER_BLOCK = 16;

struct f8 { float4 a, b; };

__device__ __forceinline__ f8 ldg256_cs(const float* p)
{
    f8 r;
    asm volatile("ld.global.cs.v8.f32 {%0,%1,%2,%3,%4,%5,%6,%7}, [%8];"
                 : "=f"(r.a.x), "=f"(r.a.y), "=f"(r.a.z), "=f"(r.a.w),
                   "=f"(r.b.x), "=f"(r.b.y), "=f"(r.b.z), "=f"(r.b.w)
                 : "l"(p));
    return r;
}

__device__ __forceinline__ void stg256_cs(float* p, const f8& v)
{
    asm volatile("st.global.cs.v8.f32 [%0], {%1,%2,%3,%4,%5,%6,%7,%8};"
                 :: "l"(p),
                    "f"(v.a.x), "f"(v.a.y), "f"(v.a.z), "f"(v.a.w),
                    "f"(v.b.x), "f"(v.b.y), "f"(v.b.z), "f"(v.b.w)
                 : "memory");
}

__device__ __forceinline__ void exchange_patch(f8& v0, f8& v1, unsigned l)
{
    constexpr unsigned FULL = 0xFFFFFFFFu;

    const float b_bc = __shfl_sync(FULL, v0.a.y, 12);   // token3 col1

    const unsigned src = (l + 20u) & 31u;               // (l - 12) mod 32
    const float p0  = __shfl_sync(FULL, v0.a.x, src);   // pred col 0
    const float p3  = __shfl_sync(FULL, v0.a.w, src);   // pred col 3
    const float p4  = __shfl_sync(FULL, v0.b.x, src);   // pred col 4
    const float p10 = __shfl_sync(FULL, v1.a.z, src);   // pred col 10

    if ((l & 3u) == 0u) {                               // lane 4t owns token t
        const float x10 = v1.a.z;                       // own token col 10
        const float t   = fmaf(v0.a.w, 1.0f - x10, b_bc);   // TEMP (col 3)
        v0.a.w = t;
        v0.b.x = fmaf(v0.a.x, t, v0.b.x);                   // RAW_SUM (col 4)

        if (l >= 12u) {                                 // token t >= 3
            const float tp = fmaf(p3, 1.0f - p10, b_bc);
            v0.b.y += fmaf(p0, tp, p4);                 // RESULT += rawsum[t-3]
        }
    }
}

__global__ __launch_bounds__(THREADS)
void nibble_warp2row_kernel(const float* __restrict__ in, float* __restrict__ out)
{
    const unsigned warp = threadIdx.x >> 5;
    const unsigned l    = threadIdx.x & 31u;
    const unsigned rowA = blockIdx.x * ROWS_PER_BLOCK + warp * 2u;
    const unsigned baseA = rowA * 512u + l * 16u;   // lane owns [baseA, baseA+16)
    const unsigned baseB = baseA + 512u;            // same lane span, next row

    // front-batched: 4 x LDG.256 in flight
    f8 a0 = ldg256_cs(in + baseA);
    f8 a1 = ldg256_cs(in + baseA + 8u);
    f8 b0 = ldg256_cs(in + baseB);
    f8 b1 = ldg256_cs(in + baseB + 8u);

    exchange_patch(a0, a1, l);
    exchange_patch(b0, b1, l);

    stg256_cs(out + baseA,      a0);
    stg256_cs(out + baseA + 8u, a1);
    stg256_cs(out + baseB,      b0);
    stg256_cs(out + baseB + 8u, b1);
}

extern "C" void kernel_launch(void* const* d_in, const int* in_sizes, int n_in,
                              void* d_out, int out_size)
{
    const float* x = (const float*)d_in[0];
    float* out = (float*)d_out;

    int total = in_sizes[0];                  // BATCH * 8 * 64 floats
    if (total <= 0) total = out_size;
    const int rows = total / 512;             // 131072
    const int blocks = rows / ROWS_PER_BLOCK; // 8192
    nibble_warp2row_kernel<<<blocks, THREADS>>>(x, out);
}

// round 17
// speedup vs baseline: 1.0035x; 1.0035x over previous
#include <cuda_runtime.h>
#include <cuda_bf16.h>

// ============================================================================
// FINAL KERNEL — MultiNibbleMulStage (best measured: 81.76 us, DRAM 81%)
//
// Analytic reduction of the 4-op "nibble machine" (FFN/attn/FFN/attn with
// baked sparse weights) to 3 patched scalars per 64-float token:
//   t      = x3*(1 - x10) + x[b, tok=3, col=1]      (TEMP)
//   rawsum = x4 + x0 * t                            (RAW_SUM)
//   result = x5 + (k>=3 ? rawsum[b, k-3] : 0)       (RESULT)
// all other 61 columns: identity copy.  => pure 256MB+256MB stream.
//
// Structure: each warp holds one full 512-float batch row in registers;
// lane l owns floats [16l, 16l+16) as two 32B v8 chunks. All cross-token
// operands (b_bc, predecessor scalars) come from __shfl_sync — ZERO gather
// loads. Per thread: 2x LDG.256(cs) + 5 SHFL + few FMA + 2x STG.256(cs).
// 30 regs, occ ~77%, issue ~6%: purely DRAM-bound at the ~6.4 TB/s
// read/write-turnaround ceiling (invariant across occ 60-84% — verified).
// ============================================================================

constexpr int THREADS = 256;                  // 8 warps = 8 rows per block
constexpr int ROWS_PER_BLOCK = 8;

struct f8 { float4 a, b; };

__device__ __forceinline__ f8 ldg256_cs(const float* p)
{
    f8 r;
    asm volatile("ld.global.cs.v8.f32 {%0,%1,%2,%3,%4,%5,%6,%7}, [%8];"
                 : "=f"(r.a.x), "=f"(r.a.y), "=f"(r.a.z), "=f"(r.a.w),
                   "=f"(r.b.x), "=f"(r.b.y), "=f"(r.b.z), "=f"(r.b.w)
                 : "l"(p));
    return r;
}

__device__ __forceinline__ void stg256_cs(float* p, const f8& v)
{
    asm volatile("st.global.cs.v8.f32 [%0], {%1,%2,%3,%4,%5,%6,%7,%8};"
                 :: "l"(p),
                    "f"(v.a.x), "f"(v.a.y), "f"(v.a.z), "f"(v.a.w),
                    "f"(v.b.x), "f"(v.b.y), "f"(v.b.z), "f"(v.b.w)
                 : "memory");
}

__global__ __launch_bounds__(THREADS)
void nibble_warprow_cs_kernel(const float* __restrict__ in, float* __restrict__ out)
{
    const unsigned warp = threadIdx.x >> 5;
    const unsigned l    = threadIdx.x & 31u;
    const unsigned row  = blockIdx.x * ROWS_PER_BLOCK + warp;
    const unsigned base = row * 512u + l * 16u;   // lane owns [base, base+16)

    f8 v0 = ldg256_cs(in + base);        // chunk 2l   (token t=l/4 cols 0..7 when l%4==0)
    f8 v1 = ldg256_cs(in + base + 8u);   // chunk 2l+1 (cols 8..15 when l%4==0)

    constexpr unsigned FULL = 0xFFFFFFFFu;

    // ---- warp exchange (pre-patch values) ----
    const float b_bc = __shfl_sync(FULL, v0.a.y, 12);   // token3 col1

    const unsigned src = (l + 20u) & 31u;               // (l - 12) mod 32
    const float p0  = __shfl_sync(FULL, v0.a.x, src);   // pred col 0
    const float p3  = __shfl_sync(FULL, v0.a.w, src);   // pred col 3
    const float p4  = __shfl_sync(FULL, v0.b.x, src);   // pred col 4
    const float p10 = __shfl_sync(FULL, v1.a.z, src);   // pred col 10

    // ---- patch (lane 4t owns token t's chunk 0 in v0, chunk 1 in v1) ----
    if ((l & 3u) == 0u) {
        const float x10 = v1.a.z;                       // own token col 10
        const float t   = fmaf(v0.a.w, 1.0f - x10, b_bc);   // TEMP (col 3)
        v0.a.w = t;
        v0.b.x = fmaf(v0.a.x, t, v0.b.x);                   // RAW_SUM (col 4)

        if (l >= 12u) {                                 // token t >= 3
            const float tp = fmaf(p3, 1.0f - p10, b_bc);
            v0.b.y += fmaf(p0, tp, p4);                 // RESULT += rawsum[t-3]
        }
    }

    stg256_cs(out + base,      v0);
    stg256_cs(out + base + 8u, v1);
}

extern "C" void kernel_launch(void* const* d_in, const int* in_sizes, int n_in,
                              void* d_out, int out_size)
{
    const float* x = (const float*)d_in[0];
    float* out = (float*)d_out;

    int total = in_sizes[0];                  // BATCH * 8 * 64 floats
    if (total <= 0) total = out_size;
    const int rows = total / 512;             // 131072
    const int blocks = rows / ROWS_PER_BLOCK; // 16384
    nibble_warprow_cs_kernel<<<blocks, THREADS>>>(x, out);
}